// round 7
// baseline (speedup 1.0000x reference)
#include <cuda_runtime.h>
#include <cstdint>

#define HH 112
#define WW 112
#define CIN 64
#define COUTC 128
#define NB 32
#define NTILES 3136          // 32 images * (112/8) * (112/16)
#define GRID_CONV 304

// Scratch: quantized int8 activations (4/int32, NHWC) and weights
// [tap][cout][cin] int8 with B-side chunk swizzle pre-applied.
__device__ __align__(16) int g_Xq[NB * HH * WW * (CIN / 4)];   // ~25.7 MB
__device__ __align__(16) unsigned char g_W[9 * COUTC * CIN];   // 72 KB

// ---------------------------------------------------------------------------
__device__ __forceinline__ uint32_t smem_u32(const void* p) {
    uint32_t a;
    asm("{ .reg .u64 t; cvta.to.shared.u64 t, %1; cvt.u32.u64 %0, t; }" : "=r"(a) : "l"(p));
    return a;
}
#define CP_ASYNC16(dst, src) \
    asm volatile("cp.async.cg.shared.global [%0], [%1], 16;\n" :: "r"(dst), "l"(src))
#define CP_COMMIT()   asm volatile("cp.async.commit_group;\n" ::: "memory")
#define CP_WAIT(N)    asm volatile("cp.async.wait_group %0;\n" :: "n"(N) : "memory")
#define STS_ZERO16(dst) \
    asm volatile("st.shared.v4.b32 [%0], {%1,%1,%1,%1};" :: "r"(dst), "r"(0) : "memory")

#define LDSM_X4(r, addr)                                                          \
    asm volatile("ldmatrix.sync.aligned.m8n8.x4.shared.b16 {%0,%1,%2,%3}, [%4];"  \
        : "=r"((r)[0]), "=r"((r)[1]), "=r"((r)[2]), "=r"((r)[3]) : "r"(addr))

#define MMA_S8(c, A, B0, B1)                                                      \
    asm volatile("mma.sync.aligned.m16n8k32.row.col.s32.s8.s8.s32 "               \
        "{%0,%1,%2,%3},{%4,%5,%6,%7},{%8,%9},{%0,%1,%2,%3};"                      \
        : "+r"((c)[0]), "+r"((c)[1]), "+r"((c)[2]), "+r"((c)[3])                  \
        : "r"((A)[0]), "r"((A)[1]), "r"((A)[2]), "r"((A)[3]), "r"(B0), "r"(B1))

// ---------------------------------------------------------------------------
// Prep kernels (unchanged — exact int8 quantization)
// ---------------------------------------------------------------------------
__global__ void quant_x_kernel(const float* __restrict__ x, int nwords) {
    int i = blockIdx.x * blockDim.x + threadIdx.x;
    if (i >= nwords) return;
    float4 v = ((const float4*)x)[i];
    int a = min(127, max(-128, __float2int_rn(v.x * 128.f)));
    int b = min(127, max(-128, __float2int_rn(v.y * 128.f)));
    int c = min(127, max(-128, __float2int_rn(v.z * 128.f)));
    int d = min(127, max(-128, __float2int_rn(v.w * 128.f)));
    g_Xq[i] = (a & 0xFF) | ((b & 0xFF) << 8) | ((c & 0xFF) << 16) | (d << 24);
}

__global__ void quant_w_kernel(const float* __restrict__ k) {
    int o = blockIdx.x * blockDim.x + threadIdx.x;     // (tap*64+cin)*128+cout
    if (o >= 9 * CIN * COUTC) return;
    int tap  = o >> 13;
    int rem  = o & 8191;
    int cin  = rem >> 7;
    int cout = rem & 127;
    int q = min(127, max(-128, __float2int_rn(k[o] * 128.f)));
    int chunk = (cin >> 4) ^ ((cout >> 1) & 3);
    g_W[tap * 8192 + cout * 64 + chunk * 16 + (cin & 15)] = (unsigned char)q;
}

// ---------------------------------------------------------------------------
// Conv: persistent CTAs, 256 threads, int8 mma.sync, HALO-tile A.
// Halo = 10 h-rows x 18 w-cols x 64 cin, row stride 80B (conflict-free pad),
// double-buffered across tiles. ONE sync + ONE fill per output tile.
// SMEM: W 72KB @0, halo[2] 14464B each @73728/ @88192.  Total 102656 B.
// ---------------------------------------------------------------------------
#define HROWS      180            // 10*18
#define ROWB       80
#define HALO_B     14464          // 180*80 = 14400, padded to 128
#define SMEM_H0    73728
#define SMEM_H1    (73728 + HALO_B)
#define SMEM_BYTES (73728 + 2 * HALO_B)

__global__ __launch_bounds__(256, 2) void conv_imma_kernel(float* __restrict__ out) {
    extern __shared__ __align__(128) char smem[];
    const int tid  = threadIdx.x;
    const int wid  = tid >> 5;
    const int lane = tid & 31;
    const uint32_t sb = smem_u32(smem);
    const uint32_t sW = sb;
    const uint32_t sH[2] = { sb + SMEM_H0, sb + SMEM_H1 };

    // Prologue: all 9 weight tap tiles (72 KB)
    for (int j = tid; j < 4608; j += 256)
        CP_ASYNC16(sW + j * 16, (const char*)g_W + j * 16);

    const int m0 = (wid & 3) * 32;   // warp M offset (pixels)
    const int n0 = (wid >> 2) * 64;  // warp N offset (couts)

    // A-side ldmatrix lane geometry (halo window, 80B rows, no swizzle)
    const int p0   = m0 + (lane & 15);            // a0 pixel row
    const uint32_t laneA0 = (uint32_t)(((p0 >> 4) * 18 + (p0 & 15)) * ROWB);
    const uint32_t laneA1 = laneA0 + 18 * ROWB;   // a1 = +16 pixels = +1 h-row
    const uint32_t csA16  = (uint32_t)(lane >> 4) * 16;

    // B-side ldmatrix lane geometry (64B rows, chunk XOR swizzle)
    const int rB  = n0 + (lane >> 4) * 8 + (lane & 7);
    const int csB = (lane >> 3) & 1;
    const int swB = (rB >> 1) & 3;
    const uint32_t offB = (uint32_t)rB * 64;

    // halo fill geometry: thread t fills halo row t (t<180): 4x16B
    const int hr = tid / 18;
    const int wc = tid - hr * 18;

#define FILL_HALO(T_, buf_) do {                                                   \
        if (tid < HROWS) {                                                         \
            const int n_  = (T_) / 98;                                             \
            const int rm_ = (T_) - n_ * 98;                                        \
            const int h_  = (rm_ / 7) * 8 - 1 + hr;                                \
            const int w_  = (rm_ % 7) * 16 - 1 + wc;                               \
            const uint32_t db = sH[buf_] + (uint32_t)tid * ROWB;                   \
            if (((unsigned)h_ < HH) && ((unsigned)w_ < WW)) {                      \
                const char* src =                                                  \
                    (const char*)(g_Xq + ((size_t)(n_ * HH + h_) * WW + w_) * 16); \
                CP_ASYNC16(db,      src);                                          \
                CP_ASYNC16(db + 16, src + 16);                                     \
                CP_ASYNC16(db + 32, src + 32);                                     \
                CP_ASYNC16(db + 48, src + 48);                                     \
            } else {                                                               \
                STS_ZERO16(db); STS_ZERO16(db + 16);                               \
                STS_ZERO16(db + 32); STS_ZERO16(db + 48);                          \
            }                                                                      \
        }                                                                          \
    } while (0)

    const int T0 = blockIdx.x;
    FILL_HALO(T0, 0);
    CP_COMMIT();

    int pb = 0;
    for (int T = T0; T < NTILES; T += GRID_CONV) {
        const int n  = T / 98;
        const int rm = T - n * 98;
        const int r0 = (rm / 7) * 8;
        const int c0 = (rm % 7) * 16;

        CP_WAIT(0);
        __syncthreads();                 // halo(T) ready; compute(T-1) done everywhere

        const int Tn = T + GRID_CONV;
        if (Tn < NTILES) FILL_HALO(Tn, pb ^ 1);
        CP_COMMIT();

        int acc[2][8][4];
#pragma unroll
        for (int mt = 0; mt < 2; mt++)
#pragma unroll
            for (int nt = 0; nt < 8; nt++)
#pragma unroll
                for (int j = 0; j < 4; j++) acc[mt][nt][j] = 0;

        const uint32_t hb = sH[pb];
#pragma unroll
        for (int ky = 0; ky < 3; ky++) {
#pragma unroll
            for (int kx = 0; kx < 3; kx++) {
                const uint32_t tapoff = (uint32_t)(ky * 18 + kx) * ROWB;
                const uint32_t wb = sW + (uint32_t)(ky * 3 + kx) * 8192;
#pragma unroll
                for (int kh = 0; kh < 2; kh++) {
                    const uint32_t kc16 = (uint32_t)kh * 32;
                    uint32_t a0[4], a1[4];
                    LDSM_X4(a0, hb + laneA0 + tapoff + kc16 + csA16);
                    LDSM_X4(a1, hb + laneA1 + tapoff + kc16 + csA16);
#pragma unroll
                    for (int p = 0; p < 4; p++) {
                        uint32_t b[4];
                        LDSM_X4(b, wb + offB + (uint32_t)p * 1024 +
                                   (uint32_t)(((kh * 2 + csB) ^ swB) * 16));
                        MMA_S8(acc[0][2 * p],     a0, b[0], b[1]);
                        MMA_S8(acc[0][2 * p + 1], a0, b[2], b[3]);
                        MMA_S8(acc[1][2 * p],     a1, b[0], b[1]);
                        MMA_S8(acc[1][2 * p + 1], a1, b[2], b[3]);
                    }
                }
            }
        }

        // Epilogue: out = floor(acc * 2^-7) * 2^-7   (exact)
#pragma unroll
        for (int mt = 0; mt < 2; mt++) {
            const int px1 = m0 + mt * 16 + (lane >> 2);
            const int px2 = px1 + 8;
            float* o1 = out + (((size_t)(n * HH + r0 + (px1 >> 4)) * WW +
                                (c0 + (px1 & 15))) << 7);
            float* o2 = out + (((size_t)(n * HH + r0 + (px2 >> 4)) * WW +
                                (c0 + (px2 & 15))) << 7);
            const int col = n0 + (lane & 3) * 2;
#pragma unroll
            for (int nt = 0; nt < 8; nt++) {
                float2 v;
                v.x = floorf((float)acc[mt][nt][0] * 0.0078125f) * 0.0078125f;
                v.y = floorf((float)acc[mt][nt][1] * 0.0078125f) * 0.0078125f;
                *(float2*)(o1 + col + nt * 8) = v;
                v.x = floorf((float)acc[mt][nt][2] * 0.0078125f) * 0.0078125f;
                v.y = floorf((float)acc[mt][nt][3] * 0.0078125f) * 0.0078125f;
                *(float2*)(o2 + col + nt * 8) = v;
            }
        }
        pb ^= 1;
    }
}

extern "C" void kernel_launch(void* const* d_in, const int* in_sizes, int n_in,
                              void* d_out, int out_size) {
    const float* x = (const float*)d_in[0];   // [32,112,112,64] fp32 NHWC
    const float* k = (const float*)d_in[1];   // [3,3,64,128] fp32 HWIO
    float* out = (float*)d_out;               // [32,112,112,128] fp32

    cudaFuncSetAttribute(conv_imma_kernel,
                         cudaFuncAttributeMaxDynamicSharedMemorySize, SMEM_BYTES);

    int nwords = NB * HH * WW * CIN / 4;
    quant_x_kernel<<<(nwords + 255) / 256, 256>>>(x, nwords);
    quant_w_kernel<<<(9 * CIN * COUTC + 255) / 256, 256>>>(k);
    conv_imma_kernel<<<GRID_CONV, 256, SMEM_BYTES>>>(out);
}

// round 8
// speedup vs baseline: 2.6943x; 2.6943x over previous
#include <cuda_runtime.h>
#include <cuda_bf16.h>
#include <cstdint>

#define HH 112
#define WW 112
#define CIN 64
#define COUTC 128
#define NB 32
#define NTILES 3136          // 32 images * (112/8) * (112/16)
#define GRID_CONV 152

// Scratch: quantized activations as integer-valued bf16 (exact), NHWC; and
// weights [tap][cout][cin] bf16 with the XOR-8 smem swizzle pre-applied.
__device__ __align__(16) __nv_bfloat16 g_Xb[NB * HH * WW * CIN];  // ~51.4 MB
__device__ __align__(16) __nv_bfloat16 g_Wb[9 * COUTC * CIN];     // 144 KB

// ---------------------------------------------------------------------------
__device__ __forceinline__ uint32_t smem_u32(const void* p) {
    uint32_t a;
    asm("{ .reg .u64 t; cvta.to.shared.u64 t, %1; cvt.u32.u64 %0, t; }" : "=r"(a) : "l"(p));
    return a;
}
#define CP_ASYNC16(dst, src) \
    asm volatile("cp.async.cg.shared.global [%0], [%1], 16;\n" :: "r"(dst), "l"(src))
#define CP_COMMIT()   asm volatile("cp.async.commit_group;\n" ::: "memory")
#define CP_WAIT(N)    asm volatile("cp.async.wait_group %0;\n" :: "n"(N) : "memory")
#define STS_ZERO16(dst) \
    asm volatile("st.shared.v4.b32 [%0], {%1,%1,%1,%1};" :: "r"(dst), "r"(0) : "memory")

#define LDSM_X4(r, addr)                                                          \
    asm volatile("ldmatrix.sync.aligned.m8n8.x4.shared.b16 {%0,%1,%2,%3}, [%4];"  \
        : "=r"((r)[0]), "=r"((r)[1]), "=r"((r)[2]), "=r"((r)[3]) : "r"(addr))

#define MMA_BF16(c, A, B0, B1)                                                    \
    asm volatile("mma.sync.aligned.m16n8k16.row.col.f32.bf16.bf16.f32 "           \
        "{%0,%1,%2,%3},{%4,%5,%6,%7},{%8,%9},{%0,%1,%2,%3};"                      \
        : "+f"((c)[0]), "+f"((c)[1]), "+f"((c)[2]), "+f"((c)[3])                  \
        : "r"((A)[0]), "r"((A)[1]), "r"((A)[2]), "r"((A)[3]), "r"(B0), "r"(B1))

// ---------------------------------------------------------------------------
// Prep: quantize activations -> integer-valued bf16, NHWC preserved
// ---------------------------------------------------------------------------
__global__ void quant_x_kernel(const float* __restrict__ x, int n4) {
    int i = blockIdx.x * blockDim.x + threadIdx.x;
    if (i >= n4) return;
    float4 v = ((const float4*)x)[i];
    int a = min(127, max(-128, __float2int_rn(v.x * 128.f)));
    int b = min(127, max(-128, __float2int_rn(v.y * 128.f)));
    int c = min(127, max(-128, __float2int_rn(v.z * 128.f)));
    int d = min(127, max(-128, __float2int_rn(v.w * 128.f)));
    __nv_bfloat162 lo = __halves2bfloat162(__float2bfloat16((float)a), __float2bfloat16((float)b));
    __nv_bfloat162 hi = __halves2bfloat162(__float2bfloat16((float)c), __float2bfloat16((float)d));
    uint2 u;
    u.x = reinterpret_cast<unsigned&>(lo);
    u.y = reinterpret_cast<unsigned&>(hi);
    ((uint2*)g_Xb)[i] = u;
}

// ---------------------------------------------------------------------------
// Prep: quantize weights HWIO -> [tap][cout][cin] bf16, 128B rows, chunk c
// (16B = 8 bf16) of row r stored at c ^ (r & 7)  (pre-swizzled).
// ---------------------------------------------------------------------------
__global__ void quant_w_kernel(const float* __restrict__ k) {
    int o = blockIdx.x * blockDim.x + threadIdx.x;     // (tap*64+cin)*128+cout
    if (o >= 9 * CIN * COUTC) return;
    int tap  = o >> 13;
    int rem  = o & 8191;
    int cin  = rem >> 7;
    int cout = rem & 127;
    int q = min(127, max(-128, __float2int_rn(k[o] * 128.f)));
    int chunk = (cin >> 3) ^ (cout & 7);
    g_Wb[tap * 8192 + cout * 64 + chunk * 8 + (cin & 7)] = __float2bfloat16((float)q);
}

// ---------------------------------------------------------------------------
// Conv: persistent CTAs (152, 1/SM), 256 threads, bf16 mma.sync m16n8k16.
// W resident: 9 x 16KB = 144KB @0.  A: 3-slot ring of 16KB tap tiles.
// One __syncthreads per tap (3-stage cp.async ring).
// Per warp tile: M32 x N64; 36 k-steps; 576 HMMA + 216 LDSM per output tile.
// ---------------------------------------------------------------------------
#define SMEM_A     147456
#define ABUF       16384
#define SMEM_BYTES (147456 + 3 * 16384)   // 196608

__global__ __launch_bounds__(256, 1) void conv_hmma_kernel(float* __restrict__ out) {
    extern __shared__ __align__(128) char smem[];
    const int tid  = threadIdx.x;
    const int wid  = tid >> 5;
    const int lane = tid & 31;
    const uint32_t sb = smem_u32(smem);
    const uint32_t sW = sb;
    const uint32_t sA[3] = { sb + SMEM_A, sb + SMEM_A + ABUF, sb + SMEM_A + 2 * ABUF };

    const int m0 = (wid & 3) * 32;   // warp M offset (pixels)
    const int n0 = (wid >> 2) * 64;  // warp N offset (couts)

    // ldmatrix lane geometry (row & 7 == lane & 7 for both A and B)
    const int sw7 = lane & 7;
    const uint32_t offA0 = (uint32_t)(m0 + (lane & 15)) * 128;        // mt=0
    const uint32_t offA1 = offA0 + 16 * 128;                          // mt=1
    const uint32_t csA   = (uint32_t)(lane >> 4);                     // 0/1
    const uint32_t offB  = (uint32_t)(n0 + ((lane >> 4) & 1) * 8 + (lane & 7)) * 128;
    const uint32_t csB   = (uint32_t)((lane >> 3) & 1);               // 0/1

    // fill geometry: thread t fills row t>>1 (128 rows), half (t&1) = 4 chunks
    const int fr  = tid >> 1;
    const int fh  = tid & 1;
    const int frr = fr >> 4;
    const int fcc = fr & 15;
    const int fsw = fr & 7;

    // fill (tileIdx, tap) into buffer buf
#define FILL(T_, tap_, buf_) do {                                                  \
        const int n_  = (T_) / 98;                                                 \
        const int rm_ = (T_) - n_ * 98;                                            \
        const int ky_ = (tap_) / 3, kx_ = (tap_) - ky_ * 3;                        \
        const int h_  = (rm_ / 7) * 8 + frr + ky_ - 1;                             \
        const int w_  = (rm_ % 7) * 16 + fcc + kx_ - 1;                            \
        const uint32_t db = sA[buf_] + (uint32_t)fr * 128;                         \
        if (((unsigned)h_ < HH) && ((unsigned)w_ < WW)) {                          \
            const char* src = (const char*)g_Xb +                                  \
                ((size_t)(n_ * HH + h_) * WW + w_) * 128 + fh * 64;                \
            CP_ASYNC16(db + (uint32_t)(((fh * 4 + 0) ^ fsw) * 16), src);           \
            CP_ASYNC16(db + (uint32_t)(((fh * 4 + 1) ^ fsw) * 16), src + 16);      \
            CP_ASYNC16(db + (uint32_t)(((fh * 4 + 2) ^ fsw) * 16), src + 32);      \
            CP_ASYNC16(db + (uint32_t)(((fh * 4 + 3) ^ fsw) * 16), src + 48);      \
        } else {                                                                   \
            STS_ZERO16(db + (uint32_t)(((fh * 4 + 0) ^ fsw) * 16));                \
            STS_ZERO16(db + (uint32_t)(((fh * 4 + 1) ^ fsw) * 16));                \
            STS_ZERO16(db + (uint32_t)(((fh * 4 + 2) ^ fsw) * 16));                \
            STS_ZERO16(db + (uint32_t)(((fh * 4 + 3) ^ fsw) * 16));                \
        }                                                                          \
    } while (0)

    // Prologue: group0 = W (144KB) + fill(tile0, tap0);  group1 = fill(tile0, tap1)
    for (int j = tid; j < 9216; j += 256)
        CP_ASYNC16(sW + j * 16, (const char*)g_Wb + j * 16);
    const int T0 = blockIdx.x;
    FILL(T0, 0, 0);
    CP_COMMIT();
    FILL(T0, 1, 1);
    CP_COMMIT();

    int slot = 0;
    for (int T = T0; T < NTILES; T += GRID_CONV) {
        const int n  = T / 98;
        const int rm = T - n * 98;
        const int r0 = (rm / 7) * 8;
        const int c0 = (rm % 7) * 16;

        float acc[2][8][4];
#pragma unroll
        for (int mt = 0; mt < 2; mt++)
#pragma unroll
            for (int nt = 0; nt < 8; nt++)
#pragma unroll
                for (int j = 0; j < 4; j++) acc[mt][nt][j] = 0.f;

#pragma unroll 1
        for (int tap = 0; tap < 9; tap++) {
            CP_WAIT(1);              // stage g done (g+1 may be in flight)
            __syncthreads();         // all warps done with stage g-1's slot

            // prefetch stage g+2 into the slot freed at stage g-1
            {
                int ft = tap + 2, fT = T;
                if (ft >= 9) { ft -= 9; fT = T + GRID_CONV; }
                if (fT < NTILES) FILL(fT, ft, (slot + 2) % 3);
                CP_COMMIT();
            }

            const uint32_t ab = sA[slot];
            const uint32_t wb = sW + (uint32_t)tap * 16384;
#pragma unroll
            for (int ks = 0; ks < 4; ks++) {
                uint32_t a0[4], a1[4];
                const uint32_t ca = (uint32_t)(((2 * ks + csA) ^ sw7) * 16);
                LDSM_X4(a0, ab + offA0 + ca);
                LDSM_X4(a1, ab + offA1 + ca);
                const uint32_t cb = (uint32_t)(((2 * ks + csB) ^ sw7) * 16);
#pragma unroll
                for (int p = 0; p < 4; p++) {
                    uint32_t b[4];
                    LDSM_X4(b, wb + offB + (uint32_t)p * 2048 + cb);
                    MMA_BF16(acc[0][2 * p],     a0, b[0], b[1]);
                    MMA_BF16(acc[0][2 * p + 1], a0, b[2], b[3]);
                    MMA_BF16(acc[1][2 * p],     a1, b[0], b[1]);
                    MMA_BF16(acc[1][2 * p + 1], a1, b[2], b[3]);
                }
            }
            slot = (slot + 1) % 3;
        }

        // Epilogue: out = floor(acc * 2^-7) * 2^-7   (exact)
#pragma unroll
        for (int mt = 0; mt < 2; mt++) {
            const int px1 = m0 + mt * 16 + (lane >> 2);
            const int px2 = px1 + 8;
            float* o1 = out + (((size_t)(n * HH + r0 + (px1 >> 4)) * WW +
                                (c0 + (px1 & 15))) << 7);
            float* o2 = out + (((size_t)(n * HH + r0 + (px2 >> 4)) * WW +
                                (c0 + (px2 & 15))) << 7);
            const int col = n0 + (lane & 3) * 2;
#pragma unroll
            for (int nt = 0; nt < 8; nt++) {
                float2 v;
                v.x = floorf(acc[mt][nt][0] * 0.0078125f) * 0.0078125f;
                v.y = floorf(acc[mt][nt][1] * 0.0078125f) * 0.0078125f;
                *(float2*)(o1 + col + nt * 8) = v;
                v.x = floorf(acc[mt][nt][2] * 0.0078125f) * 0.0078125f;
                v.y = floorf(acc[mt][nt][3] * 0.0078125f) * 0.0078125f;
                *(float2*)(o2 + col + nt * 8) = v;
            }
        }
    }
}

extern "C" void kernel_launch(void* const* d_in, const int* in_sizes, int n_in,
                              void* d_out, int out_size) {
    const float* x = (const float*)d_in[0];   // [32,112,112,64] fp32 NHWC
    const float* k = (const float*)d_in[1];   // [3,3,64,128] fp32 HWIO
    float* out = (float*)d_out;               // [32,112,112,128] fp32

    cudaFuncSetAttribute(conv_hmma_kernel,
                         cudaFuncAttributeMaxDynamicSharedMemorySize, SMEM_BYTES);

    int n4 = NB * HH * WW * CIN / 4;
    quant_x_kernel<<<(n4 + 255) / 256, 256>>>(x, n4);
    quant_w_kernel<<<(9 * CIN * COUTC + 255) / 256, 256>>>(k);
    conv_hmma_kernel<<<GRID_CONV, 256, SMEM_BYTES>>>(out);
}

// round 9
// speedup vs baseline: 2.9856x; 1.1081x over previous
#include <cuda_runtime.h>
#include <cuda_bf16.h>
#include <cstdint>

#define HH 112
#define WW 112
#define CIN 64
#define COUTC 128
#define NB 32
#define NTILES 1568          // 32 images * 7 * 7 tiles of 16x16 px
#define GRID_CONV 152

// Scratch: quantized activations as integer-valued bf16 (exact), NHWC; and
// weights [tap][cout][cin] bf16 with the XOR-8 smem swizzle pre-applied.
__device__ __align__(16) __nv_bfloat16 g_Xb[NB * HH * WW * CIN];  // ~51.4 MB
__device__ __align__(16) __nv_bfloat16 g_Wb[9 * COUTC * CIN];     // 144 KB

// ---------------------------------------------------------------------------
__device__ __forceinline__ uint32_t smem_u32(const void* p) {
    uint32_t a;
    asm("{ .reg .u64 t; cvta.to.shared.u64 t, %1; cvt.u32.u64 %0, t; }" : "=r"(a) : "l"(p));
    return a;
}
#define CP_ASYNC16(dst, src) \
    asm volatile("cp.async.cg.shared.global [%0], [%1], 16;\n" :: "r"(dst), "l"(src))
#define CP_COMMIT()   asm volatile("cp.async.commit_group;\n" ::: "memory")
#define CP_WAIT(N)    asm volatile("cp.async.wait_group %0;\n" :: "n"(N) : "memory")
#define STS_ZERO16(dst) \
    asm volatile("st.shared.v4.b32 [%0], {%1,%1,%1,%1};" :: "r"(dst), "r"(0) : "memory")

#define LDSM_X4(r, addr)                                                          \
    asm volatile("ldmatrix.sync.aligned.m8n8.x4.shared.b16 {%0,%1,%2,%3}, [%4];"  \
        : "=r"((r)[0]), "=r"((r)[1]), "=r"((r)[2]), "=r"((r)[3]) : "r"(addr))

#define MMA_BF16(c, A, B0, B1)                                                    \
    asm volatile("mma.sync.aligned.m16n8k16.row.col.f32.bf16.bf16.f32 "           \
        "{%0,%1,%2,%3},{%4,%5,%6,%7},{%8,%9},{%0,%1,%2,%3};"                      \
        : "+f"((c)[0]), "+f"((c)[1]), "+f"((c)[2]), "+f"((c)[3])                  \
        : "r"((A)[0]), "r"((A)[1]), "r"((A)[2]), "r"((A)[3]), "r"(B0), "r"(B1))

__device__ __forceinline__ unsigned q_bf16x2(float a, float b) {
    int qa = min(127, max(-128, __float2int_rn(a * 128.f)));
    int qb = min(127, max(-128, __float2int_rn(b * 128.f)));
    __nv_bfloat162 p = __halves2bfloat162(__float2bfloat16((float)qa),
                                          __float2bfloat16((float)qb));
    return reinterpret_cast<unsigned&>(p);
}

// ---------------------------------------------------------------------------
// Fused prep: blocks [0,36) quantize+relayout W; the rest quantize X
// (8 floats per thread: 2x LDG.128 -> 1x STG.128).
// ---------------------------------------------------------------------------
#define WBLK 36
__global__ void quant_prep_kernel(const float* __restrict__ x,
                                  const float* __restrict__ k) {
    const int b = blockIdx.x;
    if (b < WBLK) {
        int o = b * 2048 + threadIdx.x;          // 36*2048 = 73728 = 9*64*128
#pragma unroll
        for (int j = 0; j < 8; j++, o += 256) {
            int tap  = o >> 13;
            int rem  = o & 8191;
            int cin  = rem >> 7;
            int cout = rem & 127;
            int q = min(127, max(-128, __float2int_rn(k[o] * 128.f)));
            int chunk = (cin >> 3) ^ (cout & 7);
            g_Wb[tap * 8192 + cout * 64 + chunk * 8 + (cin & 7)] =
                __float2bfloat16((float)q);
        }
        return;
    }
    const size_t i = (size_t)(b - WBLK) * 256 + threadIdx.x;   // 8-float group
    const float4* xv = (const float4*)x;
    float4 v0 = xv[i * 2];
    float4 v1 = xv[i * 2 + 1];
    uint4 u;
    u.x = q_bf16x2(v0.x, v0.y);
    u.y = q_bf16x2(v0.z, v0.w);
    u.z = q_bf16x2(v1.x, v1.y);
    u.w = q_bf16x2(v1.z, v1.w);
    ((uint4*)g_Xb)[i] = u;
}

// ---------------------------------------------------------------------------
// Conv: persistent CTAs (152, 1/SM), 512 threads (4 warps/SMSP),
// bf16 mma.sync m16n8k16.  CTA tile: 256 px (16x16) x 128 cout.
// W resident: 144KB @0.  A: 2 x 32KB tap tiles (double buffer).
// Warp grid 8(M) x 2(N); warp tile M32 x N64.
// ---------------------------------------------------------------------------
#define SMEM_A     147456
#define ABUF       32768
#define SMEM_BYTES (147456 + 2 * ABUF)   // 212992

__global__ __launch_bounds__(512, 1) void conv_hmma_kernel(float* __restrict__ out) {
    extern __shared__ __align__(128) char smem[];
    const int tid  = threadIdx.x;
    const int wid  = tid >> 5;
    const int lane = tid & 31;
    const uint32_t sb = smem_u32(smem);
    const uint32_t sW = sb;
    const uint32_t sA[2] = { sb + SMEM_A, sb + SMEM_A + ABUF };

    const int m0 = (wid & 7) * 32;   // warp M offset (pixels, 0..224)
    const int n0 = (wid >> 3) * 64;  // warp N offset (couts)

    // ldmatrix lane geometry (XOR-8 chunk swizzle on 128B rows)
    const int sw7 = lane & 7;
    const uint32_t offA0 = (uint32_t)(m0 + (lane & 15)) * 128;        // mt=0
    const uint32_t offA1 = offA0 + 16 * 128;                          // mt=1
    const uint32_t csA   = (uint32_t)(lane >> 4);                     // 0/1
    const uint32_t offB  = (uint32_t)(n0 + ((lane >> 4) & 1) * 8 + (lane & 7)) * 128;
    const uint32_t csB   = (uint32_t)((lane >> 3) & 1);               // 0/1

    // fill geometry: thread t fills A row t>>1 (256 rows), half t&1
    const int fr  = tid >> 1;
    const int fh  = tid & 1;
    const int frr = fr >> 4;          // 0..15 (h within tile)
    const int fcc = fr & 15;          // 0..15 (w within tile)
    const int fsw = fr & 7;

#define FILL(T_, tap_, buf_) do {                                                  \
        const int n_  = (T_) / 49;                                                 \
        const int rm_ = (T_) - n_ * 49;                                            \
        const int ky_ = (tap_) / 3, kx_ = (tap_) - ky_ * 3;                        \
        const int h_  = (rm_ / 7) * 16 + frr + ky_ - 1;                            \
        const int w_  = (rm_ % 7) * 16 + fcc + kx_ - 1;                            \
        const uint32_t db = sA[buf_] + (uint32_t)fr * 128;                         \
        if (((unsigned)h_ < HH) && ((unsigned)w_ < WW)) {                          \
            const char* src = (const char*)g_Xb +                                  \
                ((size_t)(n_ * HH + h_) * WW + w_) * 128 + fh * 64;                \
            CP_ASYNC16(db + (uint32_t)(((fh * 4 + 0) ^ fsw) * 16), src);           \
            CP_ASYNC16(db + (uint32_t)(((fh * 4 + 1) ^ fsw) * 16), src + 16);      \
            CP_ASYNC16(db + (uint32_t)(((fh * 4 + 2) ^ fsw) * 16), src + 32);      \
            CP_ASYNC16(db + (uint32_t)(((fh * 4 + 3) ^ fsw) * 16), src + 48);      \
        } else {                                                                   \
            STS_ZERO16(db + (uint32_t)(((fh * 4 + 0) ^ fsw) * 16));                \
            STS_ZERO16(db + (uint32_t)(((fh * 4 + 1) ^ fsw) * 16));                \
            STS_ZERO16(db + (uint32_t)(((fh * 4 + 2) ^ fsw) * 16));                \
            STS_ZERO16(db + (uint32_t)(((fh * 4 + 3) ^ fsw) * 16));                \
        }                                                                          \
    } while (0)

    // Prologue: resident W (144KB) + first A tap
    for (int j = tid; j < 9216; j += 512)
        CP_ASYNC16(sW + j * 16, (const char*)g_Wb + j * 16);
    const int T0 = blockIdx.x;
    FILL(T0, 0, 0);
    CP_COMMIT();

    int buf = 0;
    for (int T = T0; T < NTILES; T += GRID_CONV) {
        const int n  = T / 49;
        const int rm = T - n * 49;
        const int r0 = (rm / 7) * 16;
        const int c0 = (rm % 7) * 16;

        float acc[2][8][4];
#pragma unroll
        for (int mt = 0; mt < 2; mt++)
#pragma unroll
            for (int nt = 0; nt < 8; nt++)
#pragma unroll
                for (int j = 0; j < 4; j++) acc[mt][nt][j] = 0.f;

#pragma unroll 1
        for (int tap = 0; tap < 9; tap++) {
            CP_WAIT(0);              // fill(tap) complete
            __syncthreads();         // all warps past compute(tap-1) -> buf^1 free

            // prefetch next stage (next tap, or next tile's tap 0)
            if (tap < 8) {
                FILL(T, tap + 1, buf ^ 1);
                CP_COMMIT();
            } else if (T + GRID_CONV < NTILES) {
                FILL(T + GRID_CONV, 0, buf ^ 1);
                CP_COMMIT();
            }

            const uint32_t ab = sA[buf];
            const uint32_t wb = sW + (uint32_t)tap * 16384;
#pragma unroll
            for (int ks = 0; ks < 4; ks++) {
                uint32_t a0[4], a1[4];
                const uint32_t ca = (uint32_t)(((2 * ks + csA) ^ sw7) * 16);
                LDSM_X4(a0, ab + offA0 + ca);
                LDSM_X4(a1, ab + offA1 + ca);
                const uint32_t cb = (uint32_t)(((2 * ks + csB) ^ sw7) * 16);
#pragma unroll
                for (int p = 0; p < 4; p++) {
                    uint32_t b[4];
                    LDSM_X4(b, wb + offB + (uint32_t)p * 2048 + cb);
                    MMA_BF16(acc[0][2 * p],     a0, b[0], b[1]);
                    MMA_BF16(acc[0][2 * p + 1], a0, b[2], b[3]);
                    MMA_BF16(acc[1][2 * p],     a1, b[0], b[1]);
                    MMA_BF16(acc[1][2 * p + 1], a1, b[2], b[3]);
                }
            }
            buf ^= 1;
        }

        // Epilogue: out = floor(acc * 2^-7) * 2^-7   (exact)
#pragma unroll
        for (int mt = 0; mt < 2; mt++) {
            const int px1 = m0 + mt * 16 + (lane >> 2);
            const int px2 = px1 + 8;
            float* o1 = out + (((size_t)(n * HH + r0 + (px1 >> 4)) * WW +
                                (c0 + (px1 & 15))) << 7);
            float* o2 = out + (((size_t)(n * HH + r0 + (px2 >> 4)) * WW +
                                (c0 + (px2 & 15))) << 7);
            const int col = n0 + (lane & 3) * 2;
#pragma unroll
            for (int nt = 0; nt < 8; nt++) {
                float2 v;
                v.x = floorf(acc[mt][nt][0] * 0.0078125f) * 0.0078125f;
                v.y = floorf(acc[mt][nt][1] * 0.0078125f) * 0.0078125f;
                *(float2*)(o1 + col + nt * 8) = v;
                v.x = floorf(acc[mt][nt][2] * 0.0078125f) * 0.0078125f;
                v.y = floorf(acc[mt][nt][3] * 0.0078125f) * 0.0078125f;
                *(float2*)(o2 + col + nt * 8) = v;
            }
        }
    }
}

extern "C" void kernel_launch(void* const* d_in, const int* in_sizes, int n_in,
                              void* d_out, int out_size) {
    const float* x = (const float*)d_in[0];   // [32,112,112,64] fp32 NHWC
    const float* k = (const float*)d_in[1];   // [3,3,64,128] fp32 HWIO
    float* out = (float*)d_out;               // [32,112,112,128] fp32

    cudaFuncSetAttribute(conv_hmma_kernel,
                         cudaFuncAttributeMaxDynamicSharedMemorySize, SMEM_BYTES);

    int nx8 = NB * HH * WW * CIN / 8;         // 8 floats per thread
    quant_prep_kernel<<<WBLK + nx8 / 256, 256>>>(x, k);
    conv_hmma_kernel<<<GRID_CONV, 512, SMEM_BYTES>>>(out);
}

// round 11
// speedup vs baseline: 3.8061x; 1.2748x over previous
#include <cuda_runtime.h>
#include <cuda_bf16.h>
#include <cstdint>

#define HH 112
#define WW 112
#define CIN 64
#define COUTC 128
#define NB 32
#define NTILES 1568          // 32 images * 7 * 7 tiles of 16x16 px
#define GRID_CONV 152

// Scratch: quantized activations as integer-valued bf16 (exact), NHWC; and
// weights [tap][cout][cin] bf16 with the XOR-8 smem swizzle pre-applied.
__device__ __align__(16) __nv_bfloat16 g_Xb[NB * HH * WW * CIN];  // ~51.4 MB
__device__ __align__(16) __nv_bfloat16 g_Wb[9 * COUTC * CIN];     // 144 KB

// ---------------------------------------------------------------------------
__device__ __forceinline__ uint32_t smem_u32(const void* p) {
    uint32_t a;
    asm("{ .reg .u64 t; cvta.to.shared.u64 t, %1; cvt.u32.u64 %0, t; }" : "=r"(a) : "l"(p));
    return a;
}
#define CP_ASYNC16(dst, src) \
    asm volatile("cp.async.cg.shared.global [%0], [%1], 16;\n" :: "r"(dst), "l"(src))
#define CP_COMMIT()   asm volatile("cp.async.commit_group;\n" ::: "memory")
#define CP_WAIT(N)    asm volatile("cp.async.wait_group %0;\n" :: "n"(N) : "memory")
#define STS_ZERO16(dst) \
    asm volatile("st.shared.v4.b32 [%0], {%1,%1,%1,%1};" :: "r"(dst), "r"(0) : "memory")

#define LDSM_X4(r, addr)                                                          \
    asm volatile("ldmatrix.sync.aligned.m8n8.x4.shared.b16 {%0,%1,%2,%3}, [%4];"  \
        : "=r"((r)[0]), "=r"((r)[1]), "=r"((r)[2]), "=r"((r)[3]) : "r"(addr))

#define MMA_BF16(c, A, B0, B1)                                                    \
    asm volatile("mma.sync.aligned.m16n8k16.row.col.f32.bf16.bf16.f32 "           \
        "{%0,%1,%2,%3},{%4,%5,%6,%7},{%8,%9},{%0,%1,%2,%3};"                      \
        : "+f"((c)[0]), "+f"((c)[1]), "+f"((c)[2]), "+f"((c)[3])                  \
        : "r"((A)[0]), "r"((A)[1]), "r"((A)[2]), "r"((A)[3]), "r"(B0), "r"(B1))

__device__ __forceinline__ unsigned q_bf16x2(float a, float b) {
    int qa = min(127, max(-128, __float2int_rn(a * 128.f)));
    int qb = min(127, max(-128, __float2int_rn(b * 128.f)));
    __nv_bfloat162 p = __halves2bfloat162(__float2bfloat16((float)qa),
                                          __float2bfloat16((float)qb));
    return reinterpret_cast<unsigned&>(p);
}

// ---------------------------------------------------------------------------
// Fused prep: blocks [0,36) quantize+relayout W; the rest quantize X.
// ---------------------------------------------------------------------------
#define WBLK 36
__global__ void quant_prep_kernel(const float* __restrict__ x,
                                  const float* __restrict__ k) {
    const int b = blockIdx.x;
    if (b < WBLK) {
        int o = b * 2048 + threadIdx.x;          // 36*2048 = 73728 = 9*64*128
#pragma unroll
        for (int j = 0; j < 8; j++, o += 256) {
            int tap  = o >> 13;
            int rem  = o & 8191;
            int cin  = rem >> 7;
            int cout = rem & 127;
            int q = min(127, max(-128, __float2int_rn(k[o] * 128.f)));
            int chunk = (cin >> 3) ^ (cout & 7);
            g_Wb[tap * 8192 + cout * 64 + chunk * 8 + (cin & 7)] =
                __float2bfloat16((float)q);
        }
        return;
    }
    const size_t i = (size_t)(b - WBLK) * 256 + threadIdx.x;   // 8-float group
    const float4* xv = (const float4*)x;
    float4 v0 = xv[i * 2];
    float4 v1 = xv[i * 2 + 1];
    uint4 u;
    u.x = q_bf16x2(v0.x, v0.y);
    u.y = q_bf16x2(v0.z, v0.w);
    u.z = q_bf16x2(v1.x, v1.y);
    u.w = q_bf16x2(v1.z, v1.w);
    ((uint4*)g_Xb)[i] = u;
}

// ---------------------------------------------------------------------------
// Conv: persistent CTAs (152, 1/SM), 512 threads, bf16 mma.sync m16n8k16.
// CTA tile: 256 px (16x16) x 128 cout.  W resident 144KB.
// A: per kernel-ROW strips (16 h x 18 w x 64cin = 288 rows x 128B = 36KB),
// double-buffered; one fill + one __syncthreads per strip (3 per tile).
// Taps within a row are w-shifts absorbed by ldmatrix lane addresses.
// NOTE: mt=1 fragment sits +18 rows (18 % 8 == 2) -> its swizzle key differs;
// a0 and a1 each use their OWN row&7 (the R10 bug was sharing one key).
// ---------------------------------------------------------------------------
#define SMEM_S     147456
#define SBUF       36864
#define SMEM_BYTES (147456 + 2 * SBUF)   // 221184

__global__ __launch_bounds__(512, 1) void conv_hmma_kernel(float* __restrict__ out) {
    extern __shared__ __align__(128) char smem[];
    const int tid  = threadIdx.x;
    const int wid  = tid >> 5;
    const int lane = tid & 31;
    const uint32_t sb = smem_u32(smem);
    const uint32_t sW = sb;
    const uint32_t sS[2] = { sb + SMEM_S, sb + SMEM_S + SBUF };

    const int m0 = (wid & 7) * 32;   // warp M offset (pixels)
    const int n0 = (wid >> 3) * 64;  // warp N offset (couts)

    // A lane geometry: pixel p0 = m0+(lane&15) -> (hA, wA); strip row = hA*18+wA+kx
    const int p0 = m0 + (lane & 15);
    const int hA = p0 >> 4;
    const int wA = p0 & 15;
    const uint32_t csA = (uint32_t)(lane >> 4);                       // 0/1

    // B lane geometry (row&7 == lane&7)
    const int sw7B = lane & 7;
    const uint32_t offB = (uint32_t)(n0 + ((lane >> 4) & 1) * 8 + (lane & 7)) * 128;
    const uint32_t csB  = (uint32_t)((lane >> 3) & 1);                // 0/1

#define FILL_STRIP(T_, ky_, buf_) do {                                             \
        const int n_  = (T_) / 49;                                                 \
        const int rm_ = (T_) - n_ * 49;                                            \
        const int hb_ = (rm_ / 7) * 16 + (ky_) - 1;                                \
        const int wb_ = (rm_ % 7) * 16 - 1;                                        \
        _Pragma("unroll")                                                          \
        for (int jj = 0; jj < 5; jj++) {                                           \
            const int j = tid + jj * 512;                                          \
            if (j < 2304) {                                                        \
                const int row = j >> 3;                                            \
                const int c   = j & 7;                                             \
                const int rh  = row / 18;                                          \
                const int h_  = hb_ + rh;                                          \
                const int w_  = wb_ + (row - rh * 18);                             \
                const uint32_t dst = sS[buf_] + (uint32_t)row * 128 +              \
                                     (uint32_t)((c ^ (row & 7)) * 16);             \
                if (((unsigned)h_ < HH) && ((unsigned)w_ < WW)) {                  \
                    const char* src = (const char*)g_Xb +                          \
                        ((size_t)(n_ * HH + h_) * WW + w_) * 128 + c * 16;         \
                    CP_ASYNC16(dst, src);                                          \
                } else {                                                           \
                    STS_ZERO16(dst);                                               \
                }                                                                  \
            }                                                                      \
        }                                                                          \
    } while (0)

    // Prologue: resident W (144KB) + first strip
    for (int j = tid; j < 9216; j += 512)
        CP_ASYNC16(sW + j * 16, (const char*)g_Wb + j * 16);
    const int T0 = blockIdx.x;
    FILL_STRIP(T0, 0, 0);
    CP_COMMIT();

    int buf = 0;
    for (int T = T0; T < NTILES; T += GRID_CONV) {
        const int n  = T / 49;
        const int rm = T - n * 49;
        const int r0 = (rm / 7) * 16;
        const int c0 = (rm % 7) * 16;

        float acc[2][8][4];
#pragma unroll
        for (int mt = 0; mt < 2; mt++)
#pragma unroll
            for (int nt = 0; nt < 8; nt++)
#pragma unroll
                for (int j = 0; j < 4; j++) acc[mt][nt][j] = 0.f;

#pragma unroll 1
        for (int ky = 0; ky < 3; ky++) {
            CP_WAIT(0);              // strip(ky) complete
            __syncthreads();         // all warps done with buf^1

            if (ky < 2) {
                FILL_STRIP(T, ky + 1, buf ^ 1);
                CP_COMMIT();
            } else if (T + GRID_CONV < NTILES) {
                FILL_STRIP(T + GRID_CONV, 0, buf ^ 1);
                CP_COMMIT();
            }

            const uint32_t strip = sS[buf];
#pragma unroll
            for (int kx = 0; kx < 3; kx++) {
                const int rowA0 = hA * 18 + wA + kx;
                const int rowA1 = rowA0 + 18;                  // +16 pixels = +1 h
                const uint32_t aBase0 = strip + (uint32_t)rowA0 * 128;
                const uint32_t aBase1 = strip + (uint32_t)rowA1 * 128;
                const int swA0 = rowA0 & 7;
                const int swA1 = rowA1 & 7;                    // differs by 2 (18%8)
                const uint32_t wb = sW + (uint32_t)(ky * 3 + kx) * 16384;
#pragma unroll
                for (int ks = 0; ks < 4; ks++) {
                    uint32_t a0[4], a1[4];
                    LDSM_X4(a0, aBase0 + (uint32_t)(((2 * ks + csA) ^ swA0) * 16));
                    LDSM_X4(a1, aBase1 + (uint32_t)(((2 * ks + csA) ^ swA1) * 16));
                    const uint32_t cb = (uint32_t)(((2 * ks + csB) ^ sw7B) * 16);
#pragma unroll
                    for (int p = 0; p < 4; p++) {
                        uint32_t b[4];
                        LDSM_X4(b, wb + offB + (uint32_t)p * 2048 + cb);
                        MMA_BF16(acc[0][2 * p],     a0, b[0], b[1]);
                        MMA_BF16(acc[0][2 * p + 1], a0, b[2], b[3]);
                        MMA_BF16(acc[1][2 * p],     a1, b[0], b[1]);
                        MMA_BF16(acc[1][2 * p + 1], a1, b[2], b[3]);
                    }
                }
            }
            buf ^= 1;
        }

        // Epilogue: out = floor(acc * 2^-7) * 2^-7   (exact)
#pragma unroll
        for (int mt = 0; mt < 2; mt++) {
            const int px1 = m0 + mt * 16 + (lane >> 2);
            const int px2 = px1 + 8;
            float* o1 = out + (((size_t)(n * HH + r0 + (px1 >> 4)) * WW +
                                (c0 + (px1 & 15))) << 7);
            float* o2 = out + (((size_t)(n * HH + r0 + (px2 >> 4)) * WW +
                                (c0 + (px2 & 15))) << 7);
            const int col = n0 + (lane & 3) * 2;
#pragma unroll
            for (int nt = 0; nt < 8; nt++) {
                float2 v;
                v.x = floorf(acc[mt][nt][0] * 0.0078125f) * 0.0078125f;
                v.y = floorf(acc[mt][nt][1] * 0.0078125f) * 0.0078125f;
                *(float2*)(o1 + col + nt * 8) = v;
                v.x = floorf(acc[mt][nt][2] * 0.0078125f) * 0.0078125f;
                v.y = floorf(acc[mt][nt][3] * 0.0078125f) * 0.0078125f;
                *(float2*)(o2 + col + nt * 8) = v;
            }
        }
    }
}

extern "C" void kernel_launch(void* const* d_in, const int* in_sizes, int n_in,
                              void* d_out, int out_size) {
    const float* x = (const float*)d_in[0];   // [32,112,112,64] fp32 NHWC
    const float* k = (const float*)d_in[1];   // [3,3,64,128] fp32 HWIO
    float* out = (float*)d_out;               // [32,112,112,128] fp32

    cudaFuncSetAttribute(conv_hmma_kernel,
                         cudaFuncAttributeMaxDynamicSharedMemorySize, SMEM_BYTES);

    int nx8 = NB * HH * WW * CIN / 8;
    quant_prep_kernel<<<WBLK + nx8 / 256, 256>>>(x, k);
    conv_hmma_kernel<<<GRID_CONV, 512, SMEM_BYTES>>>(out);
}

// round 12
// speedup vs baseline: 3.9855x; 1.0471x over previous
#include <cuda_runtime.h>
#include <cuda_bf16.h>
#include <cstdint>

#define HH 112
#define WW 112
#define CIN 64
#define COUTC 128
#define NB 32
#define NTILES 1568          // 32 images * 7 * 7 tiles of 16x16 px
#define GRID_CONV 152

// Scratch: quantized activations as integer-valued bf16 (exact), NHWC; and
// weights [tap][cout][cin] bf16 with the XOR-8 smem swizzle pre-applied.
__device__ __align__(16) __nv_bfloat16 g_Xb[NB * HH * WW * CIN];  // ~51.4 MB
__device__ __align__(16) __nv_bfloat16 g_Wb[9 * COUTC * CIN];     // 144 KB

// ---------------------------------------------------------------------------
__device__ __forceinline__ uint32_t smem_u32(const void* p) {
    uint32_t a;
    asm("{ .reg .u64 t; cvta.to.shared.u64 t, %1; cvt.u32.u64 %0, t; }" : "=r"(a) : "l"(p));
    return a;
}
#define CP_ASYNC16(dst, src) \
    asm volatile("cp.async.cg.shared.global [%0], [%1], 16;\n" :: "r"(dst), "l"(src))
#define CP_COMMIT()   asm volatile("cp.async.commit_group;\n" ::: "memory")
#define CP_WAIT(N)    asm volatile("cp.async.wait_group %0;\n" :: "n"(N) : "memory")
#define STS_ZERO16(dst) \
    asm volatile("st.shared.v4.b32 [%0], {%1,%1,%1,%1};" :: "r"(dst), "r"(0) : "memory")

#define LDSM_X4(r, addr)                                                          \
    asm volatile("ldmatrix.sync.aligned.m8n8.x4.shared.b16 {%0,%1,%2,%3}, [%4];"  \
        : "=r"((r)[0]), "=r"((r)[1]), "=r"((r)[2]), "=r"((r)[3]) : "r"(addr))

#define MMA_BF16(c, A, B0, B1)                                                    \
    asm volatile("mma.sync.aligned.m16n8k16.row.col.f32.bf16.bf16.f32 "           \
        "{%0,%1,%2,%3},{%4,%5,%6,%7},{%8,%9},{%0,%1,%2,%3};"                      \
        : "+f"((c)[0]), "+f"((c)[1]), "+f"((c)[2]), "+f"((c)[3])                  \
        : "r"((A)[0]), "r"((A)[1]), "r"((A)[2]), "r"((A)[3]), "r"(B0), "r"(B1))

__device__ __forceinline__ unsigned q_bf16x2(float a, float b) {
    int qa = min(127, max(-128, __float2int_rn(a * 128.f)));
    int qb = min(127, max(-128, __float2int_rn(b * 128.f)));
    __nv_bfloat162 p = __halves2bfloat162(__float2bfloat16((float)qa),
                                          __float2bfloat16((float)qb));
    return reinterpret_cast<unsigned&>(p);
}

// ---------------------------------------------------------------------------
// Fused prep: blocks [0,36) quantize+relayout W; the rest quantize X.
// ---------------------------------------------------------------------------
#define WBLK 36
__global__ void quant_prep_kernel(const float* __restrict__ x,
                                  const float* __restrict__ k) {
    const int b = blockIdx.x;
    if (b < WBLK) {
        int o = b * 2048 + threadIdx.x;          // 36*2048 = 73728 = 9*64*128
#pragma unroll
        for (int j = 0; j < 8; j++, o += 256) {
            int tap  = o >> 13;
            int rem  = o & 8191;
            int cin  = rem >> 7;
            int cout = rem & 127;
            int q = min(127, max(-128, __float2int_rn(k[o] * 128.f)));
            int chunk = (cin >> 3) ^ (cout & 7);
            g_Wb[tap * 8192 + cout * 64 + chunk * 8 + (cin & 7)] =
                __float2bfloat16((float)q);
        }
        return;
    }
    const size_t i = (size_t)(b - WBLK) * 256 + threadIdx.x;   // 8-float group
    const float4* xv = (const float4*)x;
    float4 v0 = xv[i * 2];
    float4 v1 = xv[i * 2 + 1];
    uint4 u;
    u.x = q_bf16x2(v0.x, v0.y);
    u.y = q_bf16x2(v0.z, v0.w);
    u.z = q_bf16x2(v1.x, v1.y);
    u.w = q_bf16x2(v1.z, v1.w);
    ((uint4*)g_Xb)[i] = u;
}

// ---------------------------------------------------------------------------
// Conv: persistent CTAs (152, 1/SM), 512 threads, bf16 mma.sync m16n8k16.
// CTA tile: 256 px (16x16) x 128 cout.  W resident 144KB.
// A: ONE 18x18 halo per tile (324 rows x 128B = 40.5KB), double-buffered;
// one fill + ONE __syncthreads per output tile.  All 9 taps are (ky,kx)
// shifts absorbed by ldmatrix lane addresses: row = (hA+ky)*18 + wA+kx.
// Swizzle key is per-fragment row&7 (R10 lesson: never share across +18).
// ---------------------------------------------------------------------------
#define SMEM_S     147456
#define SBUF       41472                  // 324 * 128
#define SMEM_BYTES (147456 + 2 * SBUF)    // 230400

__global__ __launch_bounds__(512, 1) void conv_hmma_kernel(float* __restrict__ out) {
    extern __shared__ __align__(128) char smem[];
    const int tid  = threadIdx.x;
    const int wid  = tid >> 5;
    const int lane = tid & 31;
    const uint32_t sb = smem_u32(smem);
    const uint32_t sW = sb;
    const uint32_t sS[2] = { sb + SMEM_S, sb + SMEM_S + SBUF };

    const int m0 = (wid & 7) * 32;   // warp M offset (pixels)
    const int n0 = (wid >> 3) * 64;  // warp N offset (couts)

    // A lane geometry: pixel p0 = m0+(lane&15) -> (hA, wA)
    const int p0 = m0 + (lane & 15);
    const int hA = p0 >> 4;
    const int wA = p0 & 15;
    const uint32_t csA = (uint32_t)(lane >> 4);                       // 0/1

    // B lane geometry (row&7 == lane&7)
    const int sw7B = lane & 7;
    const uint32_t offB = (uint32_t)(n0 + ((lane >> 4) & 1) * 8 + (lane & 7)) * 128;
    const uint32_t csB  = (uint32_t)((lane >> 3) & 1);                // 0/1

#define FILL_HALO(T_, buf_) do {                                                   \
        const int n_  = (T_) / 49;                                                 \
        const int rm_ = (T_) - n_ * 49;                                            \
        const int hb_ = (rm_ / 7) * 16 - 1;                                        \
        const int wb_ = (rm_ % 7) * 16 - 1;                                        \
        _Pragma("unroll")                                                          \
        for (int jj = 0; jj < 6; jj++) {                                           \
            const int j = tid + jj * 512;                                          \
            if (j < 2592) {                                                        \
                const int row = j >> 3;                                            \
                const int c   = j & 7;                                             \
                const int rh  = row / 18;                                          \
                const int h_  = hb_ + rh;                                          \
                const int w_  = wb_ + (row - rh * 18);                             \
                const uint32_t dst = sS[buf_] + (uint32_t)row * 128 +              \
                                     (uint32_t)((c ^ (row & 7)) * 16);             \
                if (((unsigned)h_ < HH) && ((unsigned)w_ < WW)) {                  \
                    const char* src = (const char*)g_Xb +                          \
                        ((size_t)(n_ * HH + h_) * WW + w_) * 128 + c * 16;         \
                    CP_ASYNC16(dst, src);                                          \
                } else {                                                           \
                    STS_ZERO16(dst);                                               \
                }                                                                  \
            }                                                                      \
        }                                                                          \
    } while (0)

    // Prologue: resident W (144KB) + first halo
    for (int j = tid; j < 9216; j += 512)
        CP_ASYNC16(sW + j * 16, (const char*)g_Wb + j * 16);
    const int T0 = blockIdx.x;
    FILL_HALO(T0, 0);
    CP_COMMIT();

    int buf = 0;
    for (int T = T0; T < NTILES; T += GRID_CONV) {
        const int n  = T / 49;
        const int rm = T - n * 49;
        const int r0 = (rm / 7) * 16;
        const int c0 = (rm % 7) * 16;

        CP_WAIT(0);                  // halo(T) complete
        __syncthreads();             // all warps done reading buf^1 (tile T-1)

        if (T + GRID_CONV < NTILES) FILL_HALO(T + GRID_CONV, buf ^ 1);
        CP_COMMIT();

        float acc[2][8][4];
#pragma unroll
        for (int mt = 0; mt < 2; mt++)
#pragma unroll
            for (int nt = 0; nt < 8; nt++)
#pragma unroll
                for (int j = 0; j < 4; j++) acc[mt][nt][j] = 0.f;

        const uint32_t halo = sS[buf];
#pragma unroll 1
        for (int ky = 0; ky < 3; ky++) {
#pragma unroll
            for (int kx = 0; kx < 3; kx++) {
                const int rowA0 = (hA + ky) * 18 + wA + kx;
                const int rowA1 = rowA0 + 18;                  // +16 px = +1 h row
                const uint32_t aBase0 = halo + (uint32_t)rowA0 * 128;
                const uint32_t aBase1 = halo + (uint32_t)rowA1 * 128;
                const int swA0 = rowA0 & 7;
                const int swA1 = rowA1 & 7;                    // differs (18%8=2)
                const uint32_t wb = sW + (uint32_t)(ky * 3 + kx) * 16384;
#pragma unroll
                for (int ks = 0; ks < 4; ks++) {
                    uint32_t a0[4], a1[4];
                    LDSM_X4(a0, aBase0 + (uint32_t)(((2 * ks + csA) ^ swA0) * 16));
                    LDSM_X4(a1, aBase1 + (uint32_t)(((2 * ks + csA) ^ swA1) * 16));
                    const uint32_t cb = (uint32_t)(((2 * ks + csB) ^ sw7B) * 16);
#pragma unroll
                    for (int p = 0; p < 4; p++) {
                        uint32_t b[4];
                        LDSM_X4(b, wb + offB + (uint32_t)p * 2048 + cb);
                        MMA_BF16(acc[0][2 * p],     a0, b[0], b[1]);
                        MMA_BF16(acc[0][2 * p + 1], a0, b[2], b[3]);
                        MMA_BF16(acc[1][2 * p],     a1, b[0], b[1]);
                        MMA_BF16(acc[1][2 * p + 1], a1, b[2], b[3]);
                    }
                }
            }
        }

        // Epilogue: out = floor(acc * 2^-7) * 2^-7   (exact)
#pragma unroll
        for (int mt = 0; mt < 2; mt++) {
            const int px1 = m0 + mt * 16 + (lane >> 2);
            const int px2 = px1 + 8;
            float* o1 = out + (((size_t)(n * HH + r0 + (px1 >> 4)) * WW +
                                (c0 + (px1 & 15))) << 7);
            float* o2 = out + (((size_t)(n * HH + r0 + (px2 >> 4)) * WW +
                                (c0 + (px2 & 15))) << 7);
            const int col = n0 + (lane & 3) * 2;
#pragma unroll
            for (int nt = 0; nt < 8; nt++) {
                float2 v;
                v.x = floorf(acc[mt][nt][0] * 0.0078125f) * 0.0078125f;
                v.y = floorf(acc[mt][nt][1] * 0.0078125f) * 0.0078125f;
                *(float2*)(o1 + col + nt * 8) = v;
                v.x = floorf(acc[mt][nt][2] * 0.0078125f) * 0.0078125f;
                v.y = floorf(acc[mt][nt][3] * 0.0078125f) * 0.0078125f;
                *(float2*)(o2 + col + nt * 8) = v;
            }
        }
        buf ^= 1;
    }
}

extern "C" void kernel_launch(void* const* d_in, const int* in_sizes, int n_in,
                              void* d_out, int out_size) {
    const float* x = (const float*)d_in[0];   // [32,112,112,64] fp32 NHWC
    const float* k = (const float*)d_in[1];   // [3,3,64,128] fp32 HWIO
    float* out = (float*)d_out;               // [32,112,112,128] fp32

    cudaFuncSetAttribute(conv_hmma_kernel,
                         cudaFuncAttributeMaxDynamicSharedMemorySize, SMEM_BYTES);

    int nx8 = NB * HH * WW * CIN / 8;
    quant_prep_kernel<<<WBLK + nx8 / 256, 256>>>(x, k);
    conv_hmma_kernel<<<GRID_CONV, 512, SMEM_BYTES>>>(out);
}

// round 13
// speedup vs baseline: 4.0840x; 1.0247x over previous
#include <cuda_runtime.h>
#include <cuda_bf16.h>
#include <cstdint>

#define HH 112
#define WW 112
#define CIN 64
#define COUTC 128
#define NB 32
#define NTILES 1568          // 32 images * 7 * 7 tiles of 16x16 px
#define GRID_CONV 152

// Scratch: quantized activations as integer-valued bf16 (exact), NHWC; and
// weights [tap][cout][cin] bf16 with the XOR-8 smem swizzle pre-applied.
__device__ __align__(16) __nv_bfloat16 g_Xb[NB * HH * WW * CIN];  // ~51.4 MB
__device__ __align__(16) __nv_bfloat16 g_Wb[9 * COUTC * CIN];     // 144 KB

// ---------------------------------------------------------------------------
__device__ __forceinline__ uint32_t smem_u32(const void* p) {
    uint32_t a;
    asm("{ .reg .u64 t; cvta.to.shared.u64 t, %1; cvt.u32.u64 %0, t; }" : "=r"(a) : "l"(p));
    return a;
}
#define CP_ASYNC16(dst, src) \
    asm volatile("cp.async.cg.shared.global [%0], [%1], 16;\n" :: "r"(dst), "l"(src))
#define CP_COMMIT()   asm volatile("cp.async.commit_group;\n" ::: "memory")
#define CP_WAIT(N)    asm volatile("cp.async.wait_group %0;\n" :: "n"(N) : "memory")
#define STS_ZERO16(dst) \
    asm volatile("st.shared.v4.b32 [%0], {%1,%1,%1,%1};" :: "r"(dst), "r"(0) : "memory")

#define LDSM_X4(r, addr)                                                          \
    asm volatile("ldmatrix.sync.aligned.m8n8.x4.shared.b16 {%0,%1,%2,%3}, [%4];"  \
        : "=r"((r)[0]), "=r"((r)[1]), "=r"((r)[2]), "=r"((r)[3]) : "r"(addr))

#define MMA_BF16(c, A, B0, B1)                                                    \
    asm volatile("mma.sync.aligned.m16n8k16.row.col.f32.bf16.bf16.f32 "           \
        "{%0,%1,%2,%3},{%4,%5,%6,%7},{%8,%9},{%0,%1,%2,%3};"                      \
        : "+f"((c)[0]), "+f"((c)[1]), "+f"((c)[2]), "+f"((c)[3])                  \
        : "r"((A)[0]), "r"((A)[1]), "r"((A)[2]), "r"((A)[3]), "r"(B0), "r"(B1))

__device__ __forceinline__ unsigned q_bf16x2(float a, float b) {
    int qa = min(127, max(-128, __float2int_rn(a * 128.f)));
    int qb = min(127, max(-128, __float2int_rn(b * 128.f)));
    __nv_bfloat162 p = __halves2bfloat162(__float2bfloat16((float)qa),
                                          __float2bfloat16((float)qb));
    return reinterpret_cast<unsigned&>(p);
}

// ---------------------------------------------------------------------------
// Fused prep: blocks [0,36) quantize+relayout W; the rest quantize X.
// ---------------------------------------------------------------------------
#define WBLK 36
__global__ void quant_prep_kernel(const float* __restrict__ x,
                                  const float* __restrict__ k) {
    const int b = blockIdx.x;
    if (b < WBLK) {
        int o = b * 2048 + threadIdx.x;          // 36*2048 = 73728 = 9*64*128
#pragma unroll
        for (int j = 0; j < 8; j++, o += 256) {
            int tap  = o >> 13;
            int rem  = o & 8191;
            int cin  = rem >> 7;
            int cout = rem & 127;
            int q = min(127, max(-128, __float2int_rn(k[o] * 128.f)));
            int chunk = (cin >> 3) ^ (cout & 7);
            g_Wb[tap * 8192 + cout * 64 + chunk * 8 + (cin & 7)] =
                __float2bfloat16((float)q);
        }
        return;
    }
    const size_t i = (size_t)(b - WBLK) * 256 + threadIdx.x;   // 8-float group
    const float4* xv = (const float4*)x;
    float4 v0 = xv[i * 2];
    float4 v1 = xv[i * 2 + 1];
    uint4 u;
    u.x = q_bf16x2(v0.x, v0.y);
    u.y = q_bf16x2(v0.z, v0.w);
    u.z = q_bf16x2(v1.x, v1.y);
    u.w = q_bf16x2(v1.z, v1.w);
    ((uint4*)g_Xb)[i] = u;
}

// ---------------------------------------------------------------------------
// Conv: persistent CTAs (152, 1/SM), 512 threads, bf16 mma.sync m16n8k16.
// CTA tile: 256 px (16x16) x 128 cout.  W resident 144KB.
// A: ONE 18x18 halo per tile (324 rows x 128B = 40.5KB), double-buffered;
// one fill + ONE __syncthreads per output tile.
// A-FRAGMENT REUSE: frag(hA+ky+mt) -> load 4 h-row frags once per (kx,ks),
// MMA(ky,mt) uses a[ky+mt].  LDSM/warp/tile: 216 -> 192.
// Swizzle key is per-fragment row&7 (R10 lesson).
// ---------------------------------------------------------------------------
#define SMEM_S     147456
#define SBUF       41472                  // 324 * 128
#define SMEM_BYTES (147456 + 2 * SBUF)    // 230400

__global__ __launch_bounds__(512, 1) void conv_hmma_kernel(float* __restrict__ out) {
    extern __shared__ __align__(128) char smem[];
    const int tid  = threadIdx.x;
    const int wid  = tid >> 5;
    const int lane = tid & 31;
    const uint32_t sb = smem_u32(smem);
    const uint32_t sW = sb;
    const uint32_t sS[2] = { sb + SMEM_S, sb + SMEM_S + SBUF };

    const int m0 = (wid & 7) * 32;   // warp M offset (pixels)
    const int n0 = (wid >> 3) * 64;  // warp N offset (couts)

    // A lane geometry: pixel p0 = m0+(lane&15) -> (hA, wA)
    const int p0 = m0 + (lane & 15);
    const int hA = p0 >> 4;
    const int wA = p0 & 15;
    const uint32_t csA = (uint32_t)(lane >> 4);                       // 0/1

    // B lane geometry (row&7 == lane&7)
    const int sw7B = lane & 7;
    const uint32_t offB = (uint32_t)(n0 + ((lane >> 4) & 1) * 8 + (lane & 7)) * 128;
    const uint32_t csB  = (uint32_t)((lane >> 3) & 1);                // 0/1

#define FILL_HALO(T_, buf_) do {                                                   \
        const int n_  = (T_) / 49;                                                 \
        const int rm_ = (T_) - n_ * 49;                                            \
        const int hb_ = (rm_ / 7) * 16 - 1;                                        \
        const int wb_ = (rm_ % 7) * 16 - 1;                                        \
        _Pragma("unroll")                                                          \
        for (int jj = 0; jj < 6; jj++) {                                           \
            const int j = tid + jj * 512;                                          \
            if (j < 2592) {                                                        \
                const int row = j >> 3;                                            \
                const int c   = j & 7;                                             \
                const int rh  = row / 18;                                          \
                const int h_  = hb_ + rh;                                          \
                const int w_  = wb_ + (row - rh * 18);                             \
                const uint32_t dst = sS[buf_] + (uint32_t)row * 128 +              \
                                     (uint32_t)((c ^ (row & 7)) * 16);             \
                if (((unsigned)h_ < HH) && ((unsigned)w_ < WW)) {                  \
                    const char* src = (const char*)g_Xb +                          \
                        ((size_t)(n_ * HH + h_) * WW + w_) * 128 + c * 16;         \
                    CP_ASYNC16(dst, src);                                          \
                } else {                                                           \
                    STS_ZERO16(dst);                                               \
                }                                                                  \
            }                                                                      \
        }                                                                          \
    } while (0)

    // Prologue: resident W (144KB) + first halo
    for (int j = tid; j < 9216; j += 512)
        CP_ASYNC16(sW + j * 16, (const char*)g_Wb + j * 16);
    const int T0 = blockIdx.x;
    FILL_HALO(T0, 0);
    CP_COMMIT();

    int buf = 0;
    for (int T = T0; T < NTILES; T += GRID_CONV) {
        const int n  = T / 49;
        const int rm = T - n * 49;
        const int r0 = (rm / 7) * 16;
        const int c0 = (rm % 7) * 16;

        CP_WAIT(0);                  // halo(T) complete
        __syncthreads();             // all warps done reading buf^1 (tile T-1)

        if (T + GRID_CONV < NTILES) FILL_HALO(T + GRID_CONV, buf ^ 1);
        CP_COMMIT();

        float acc[2][8][4];
#pragma unroll
        for (int mt = 0; mt < 2; mt++)
#pragma unroll
            for (int nt = 0; nt < 8; nt++)
#pragma unroll
                for (int j = 0; j < 4; j++) acc[mt][nt][j] = 0.f;

        const uint32_t halo = sS[buf];
#pragma unroll 1
        for (int kx = 0; kx < 3; kx++) {
            const int rowBase = hA * 18 + wA + kx;     // h-row hA, this kx
#pragma unroll
            for (int ks = 0; ks < 4; ks++) {
                // 4 A fragments: h-rows hA..hA+3 (shared by (ky,mt): a[ky+mt])
                uint32_t a[4][4];
#pragma unroll
                for (int hr = 0; hr < 4; hr++) {
                    const int row = rowBase + hr * 18;
                    LDSM_X4(a[hr], halo + (uint32_t)row * 128 +
                            (uint32_t)(((2 * ks + csA) ^ (row & 7)) * 16));
                }
                const uint32_t cb = (uint32_t)(((2 * ks + csB) ^ sw7B) * 16);
#pragma unroll
                for (int ky = 0; ky < 3; ky++) {
                    const uint32_t wb = sW + (uint32_t)(ky * 3 + kx) * 16384;
#pragma unroll
                    for (int p = 0; p < 4; p++) {
                        uint32_t b[4];
                        LDSM_X4(b, wb + offB + (uint32_t)p * 2048 + cb);
                        MMA_BF16(acc[0][2 * p],     a[ky],     b[0], b[1]);
                        MMA_BF16(acc[0][2 * p + 1], a[ky],     b[2], b[3]);
                        MMA_BF16(acc[1][2 * p],     a[ky + 1], b[0], b[1]);
                        MMA_BF16(acc[1][2 * p + 1], a[ky + 1], b[2], b[3]);
                    }
                }
            }
        }

        // Epilogue: out = floor(acc * 2^-7) * 2^-7   (exact)
#pragma unroll
        for (int mt = 0; mt < 2; mt++) {
            const int px1 = m0 + mt * 16 + (lane >> 2);
            const int px2 = px1 + 8;
            float* o1 = out + (((size_t)(n * HH + r0 + (px1 >> 4)) * WW +
                                (c0 + (px1 & 15))) << 7);
            float* o2 = out + (((size_t)(n * HH + r0 + (px2 >> 4)) * WW +
                                (c0 + (px2 & 15))) << 7);
            const int col = n0 + (lane & 3) * 2;
#pragma unroll
            for (int nt = 0; nt < 8; nt++) {
                float2 v;
                v.x = floorf(acc[mt][nt][0] * 0.0078125f) * 0.0078125f;
                v.y = floorf(acc[mt][nt][1] * 0.0078125f) * 0.0078125f;
                *(float2*)(o1 + col + nt * 8) = v;
                v.x = floorf(acc[mt][nt][2] * 0.0078125f) * 0.0078125f;
                v.y = floorf(acc[mt][nt][3] * 0.0078125f) * 0.0078125f;
                *(float2*)(o2 + col + nt * 8) = v;
            }
        }
        buf ^= 1;
    }
}

extern "C" void kernel_launch(void* const* d_in, const int* in_sizes, int n_in,
                              void* d_out, int out_size) {
    const float* x = (const float*)d_in[0];   // [32,112,112,64] fp32 NHWC
    const float* k = (const float*)d_in[1];   // [3,3,64,128] fp32 HWIO
    float* out = (float*)d_out;               // [32,112,112,128] fp32

    cudaFuncSetAttribute(conv_hmma_kernel,
                         cudaFuncAttributeMaxDynamicSharedMemorySize, SMEM_BYTES);

    int nx8 = NB * HH * WW * CIN / 8;
    quant_prep_kernel<<<WBLK + nx8 / 256, 256>>>(x, k);
    conv_hmma_kernel<<<GRID_CONV, 512, SMEM_BYTES>>>(out);
}

// round 14
// speedup vs baseline: 4.1456x; 1.0151x over previous
#include <cuda_runtime.h>
#include <cuda_bf16.h>
#include <cstdint>

#define HH 112
#define WW 112
#define CIN 64
#define COUTC 128
#define NB 32
#define NTILES 1568          // 32 images * 7 * 7 tiles of 16x16 px
#define GRID_CONV 152

// Scratch: quantized activations as integer-valued bf16 (exact), NHWC; and
// weights [tap][cout][cin] bf16 with the XOR-8 smem swizzle pre-applied.
__device__ __align__(16) __nv_bfloat16 g_Xb[NB * HH * WW * CIN];  // ~51.4 MB
__device__ __align__(16) __nv_bfloat16 g_Wb[9 * COUTC * CIN];     // 144 KB

// ---------------------------------------------------------------------------
__device__ __forceinline__ uint32_t smem_u32(const void* p) {
    uint32_t a;
    asm("{ .reg .u64 t; cvta.to.shared.u64 t, %1; cvt.u32.u64 %0, t; }" : "=r"(a) : "l"(p));
    return a;
}
#define CP_ASYNC16(dst, src) \
    asm volatile("cp.async.cg.shared.global [%0], [%1], 16;\n" :: "r"(dst), "l"(src))
#define CP_COMMIT()   asm volatile("cp.async.commit_group;\n" ::: "memory")
#define CP_WAIT(N)    asm volatile("cp.async.wait_group %0;\n" :: "n"(N) : "memory")
#define STS_ZERO16(dst) \
    asm volatile("st.shared.v4.b32 [%0], {%1,%1,%1,%1};" :: "r"(dst), "r"(0) : "memory")

#define LDSM_X4(r, addr)                                                          \
    asm volatile("ldmatrix.sync.aligned.m8n8.x4.shared.b16 {%0,%1,%2,%3}, [%4];"  \
        : "=r"((r)[0]), "=r"((r)[1]), "=r"((r)[2]), "=r"((r)[3]) : "r"(addr))

#define MMA_BF16(c, A, B0, B1)                                                    \
    asm volatile("mma.sync.aligned.m16n8k16.row.col.f32.bf16.bf16.f32 "           \
        "{%0,%1,%2,%3},{%4,%5,%6,%7},{%8,%9},{%0,%1,%2,%3};"                      \
        : "+f"((c)[0]), "+f"((c)[1]), "+f"((c)[2]), "+f"((c)[3])                  \
        : "r"((A)[0]), "r"((A)[1]), "r"((A)[2]), "r"((A)[3]), "r"(B0), "r"(B1))

__device__ __forceinline__ unsigned q_bf16x2(float a, float b) {
    int qa = min(127, max(-128, __float2int_rn(a * 128.f)));
    int qb = min(127, max(-128, __float2int_rn(b * 128.f)));
    __nv_bfloat162 p = __halves2bfloat162(__float2bfloat16((float)qa),
                                          __float2bfloat16((float)qb));
    return reinterpret_cast<unsigned&>(p);
}

// ---------------------------------------------------------------------------
// Fused prep: blocks [0,36) quantize+relayout W; the rest quantize X.
// ---------------------------------------------------------------------------
#define WBLK 36
__global__ void quant_prep_kernel(const float* __restrict__ x,
                                  const float* __restrict__ k) {
    const int b = blockIdx.x;
    if (b < WBLK) {
        int o = b * 2048 + threadIdx.x;          // 36*2048 = 73728 = 9*64*128
#pragma unroll
        for (int j = 0; j < 8; j++, o += 256) {
            int tap  = o >> 13;
            int rem  = o & 8191;
            int cin  = rem >> 7;
            int cout = rem & 127;
            int q = min(127, max(-128, __float2int_rn(k[o] * 128.f)));
            int chunk = (cin >> 3) ^ (cout & 7);
            g_Wb[tap * 8192 + cout * 64 + chunk * 8 + (cin & 7)] =
                __float2bfloat16((float)q);
        }
        return;
    }
    const size_t i = (size_t)(b - WBLK) * 256 + threadIdx.x;   // 8-float group
    const float4* xv = (const float4*)x;
    float4 v0 = xv[i * 2];
    float4 v1 = xv[i * 2 + 1];
    uint4 u;
    u.x = q_bf16x2(v0.x, v0.y);
    u.y = q_bf16x2(v0.z, v0.w);
    u.z = q_bf16x2(v1.x, v1.y);
    u.w = q_bf16x2(v1.z, v1.w);
    ((uint4*)g_Xb)[i] = u;
}

// ---------------------------------------------------------------------------
// Conv: persistent CTAs (152, 1/SM), 512 threads, bf16 mma.sync m16n8k16.
// CTA tile: 256 px (16x16) x 128 cout.  W resident 144KB.
// A: ONE 18x18 halo per tile (40.5KB), double-buffered; 1 sync/tile.
// WARP TILE M64 x N32 (warp grid 4x4): per (kx,ks) load 6 A h-row frags
// (shared across ky+mt) and 6 B frags; each B frag feeds 8 MMAs.
// LDSM/warp/tile: 192 -> 144.  Swizzle key per-fragment row&7 (R10 lesson).
// ---------------------------------------------------------------------------
#define SMEM_S     147456
#define SBUF       41472                  // 324 * 128
#define SMEM_BYTES (147456 + 2 * SBUF)    // 230400

__global__ __launch_bounds__(512, 1) void conv_hmma_kernel(float* __restrict__ out) {
    extern __shared__ __align__(128) char smem[];
    const int tid  = threadIdx.x;
    const int wid  = tid >> 5;
    const int lane = tid & 31;
    const uint32_t sb = smem_u32(smem);
    const uint32_t sW = sb;
    const uint32_t sS[2] = { sb + SMEM_S, sb + SMEM_S + SBUF };

    const int m0 = (wid & 3) * 64;   // warp M offset (pixels)
    const int n0 = (wid >> 2) * 32;  // warp N offset (couts)

    // A lane geometry: pixel p0 = m0+(lane&15) -> (hA, wA); m0 % 16 == 0
    const int p0 = m0 + (lane & 15);
    const int hA = p0 >> 4;
    const int wA = p0 & 15;
    const uint32_t csA = (uint32_t)(lane >> 4);                       // 0/1

    // B lane geometry (row&7 == lane&7)
    const int sw7B = lane & 7;
    const uint32_t offB = (uint32_t)(n0 + ((lane >> 4) & 1) * 8 + (lane & 7)) * 128;
    const uint32_t csB  = (uint32_t)((lane >> 3) & 1);                // 0/1

#define FILL_HALO(T_, buf_) do {                                                   \
        const int n_  = (T_) / 49;                                                 \
        const int rm_ = (T_) - n_ * 49;                                            \
        const int hb_ = (rm_ / 7) * 16 - 1;                                        \
        const int wb_ = (rm_ % 7) * 16 - 1;                                        \
        _Pragma("unroll")                                                          \
        for (int jj = 0; jj < 6; jj++) {                                           \
            const int j = tid + jj * 512;                                          \
            if (j < 2592) {                                                        \
                const int row = j >> 3;                                            \
                const int c   = j & 7;                                             \
                const int rh  = row / 18;                                          \
                const int h_  = hb_ + rh;                                          \
                const int w_  = wb_ + (row - rh * 18);                             \
                const uint32_t dst = sS[buf_] + (uint32_t)row * 128 +              \
                                     (uint32_t)((c ^ (row & 7)) * 16);             \
                if (((unsigned)h_ < HH) && ((unsigned)w_ < WW)) {                  \
                    const char* src = (const char*)g_Xb +                          \
                        ((size_t)(n_ * HH + h_) * WW + w_) * 128 + c * 16;         \
                    CP_ASYNC16(dst, src);                                          \
                } else {                                                           \
                    STS_ZERO16(dst);                                               \
                }                                                                  \
            }                                                                      \
        }                                                                          \
    } while (0)

    // Prologue: resident W (144KB) + first halo
    for (int j = tid; j < 9216; j += 512)
        CP_ASYNC16(sW + j * 16, (const char*)g_Wb + j * 16);
    const int T0 = blockIdx.x;
    FILL_HALO(T0, 0);
    CP_COMMIT();

    int buf = 0;
    for (int T = T0; T < NTILES; T += GRID_CONV) {
        const int n  = T / 49;
        const int rm = T - n * 49;
        const int r0 = (rm / 7) * 16;
        const int c0 = (rm % 7) * 16;

        CP_WAIT(0);                  // halo(T) complete
        __syncthreads();             // all warps done reading buf^1 (tile T-1)

        if (T + GRID_CONV < NTILES) FILL_HALO(T + GRID_CONV, buf ^ 1);
        CP_COMMIT();

        float acc[4][4][4];          // [mt][nt][reg]
#pragma unroll
        for (int mt = 0; mt < 4; mt++)
#pragma unroll
            for (int nt = 0; nt < 4; nt++)
#pragma unroll
                for (int j = 0; j < 4; j++) acc[mt][nt][j] = 0.f;

        const uint32_t halo = sS[buf];
#pragma unroll 1
        for (int kx = 0; kx < 3; kx++) {
            const int rowBase = hA * 18 + wA + kx;
#pragma unroll
            for (int ks = 0; ks < 4; ks++) {
                // 6 A fragments: h-rows hA..hA+5 (MMA(ky,mt) uses a[ky+mt])
                uint32_t a[6][4];
#pragma unroll
                for (int hr = 0; hr < 6; hr++) {
                    const int row = rowBase + hr * 18;
                    LDSM_X4(a[hr], halo + (uint32_t)row * 128 +
                            (uint32_t)(((2 * ks + csA) ^ (row & 7)) * 16));
                }
                const uint32_t cb = (uint32_t)(((2 * ks + csB) ^ sw7B) * 16);
#pragma unroll
                for (int ky = 0; ky < 3; ky++) {
                    const uint32_t wb = sW + (uint32_t)(ky * 3 + kx) * 16384;
#pragma unroll
                    for (int p = 0; p < 2; p++) {
                        uint32_t b[4];
                        LDSM_X4(b, wb + offB + (uint32_t)p * 2048 + cb);
#pragma unroll
                        for (int mt = 0; mt < 4; mt++) {
                            MMA_BF16(acc[mt][2 * p],     a[ky + mt], b[0], b[1]);
                            MMA_BF16(acc[mt][2 * p + 1], a[ky + mt], b[2], b[3]);
                        }
                    }
                }
            }
        }

        // Epilogue: out = floor(acc * 2^-7) * 2^-7   (exact)
#pragma unroll
        for (int mt = 0; mt < 4; mt++) {
            const int px1 = m0 + mt * 16 + (lane >> 2);
            const int px2 = px1 + 8;
            float* o1 = out + (((size_t)(n * HH + r0 + (px1 >> 4)) * WW +
                                (c0 + (px1 & 15))) << 7);
            float* o2 = out + (((size_t)(n * HH + r0 + (px2 >> 4)) * WW +
                                (c0 + (px2 & 15))) << 7);
            const int col = n0 + (lane & 3) * 2;
#pragma unroll
            for (int nt = 0; nt < 4; nt++) {
                float2 v;
                v.x = floorf(acc[mt][nt][0] * 0.0078125f) * 0.0078125f;
                v.y = floorf(acc[mt][nt][1] * 0.0078125f) * 0.0078125f;
                *(float2*)(o1 + col + nt * 8) = v;
                v.x = floorf(acc[mt][nt][2] * 0.0078125f) * 0.0078125f;
                v.y = floorf(acc[mt][nt][3] * 0.0078125f) * 0.0078125f;
                *(float2*)(o2 + col + nt * 8) = v;
            }
        }
        buf ^= 1;
    }
}

extern "C" void kernel_launch(void* const* d_in, const int* in_sizes, int n_in,
                              void* d_out, int out_size) {
    const float* x = (const float*)d_in[0];   // [32,112,112,64] fp32 NHWC
    const float* k = (const float*)d_in[1];   // [3,3,64,128] fp32 HWIO
    float* out = (float*)d_out;               // [32,112,112,128] fp32

    cudaFuncSetAttribute(conv_hmma_kernel,
                         cudaFuncAttributeMaxDynamicSharedMemorySize, SMEM_BYTES);

    int nx8 = NB * HH * WW * CIN / 8;
    quant_prep_kernel<<<WBLK + nx8 / 256, 256>>>(x, k);
    conv_hmma_kernel<<<GRID_CONV, 512, SMEM_BYTES>>>(out);
}